// round 12
// baseline (speedup 1.0000x reference)
#include <cuda_runtime.h>
#include <cstdint>

// Problem constants
#define NB   32
#define LQ   2048
#define LK   2048
#define DIN  32
#define DKQ  20
#define EPS  1e-5f
// fold 1/sqrt(20) * log2(e) into q so scores are in log2 domain
#define QSCALE 0.32258572299984063f   // log2(e)/sqrt(20)
#define BIAS_MASKED (-60000.0f)       // f16-finite; ex2 -> exactly 0

// f16 storage strides (in u32 words = f16 pairs)
#define KW 20   // K row: feats 0..19, bias@20, zero-pad to 40 f16 -> 80B
#define VW 20   // V row: dims 0..31, ones-col@32, zero-pad to 40 f16 -> 80B
#define QW 16   // Q row: feats 0..19, 1.0@20, zero-pad to 32 f16 -> 64B

#define NSPLIT 2
#define LKH (LK / NSPLIT)

typedef unsigned int u32;

// Scratch (allocation-free rule: __device__ globals)
__device__ u32 d_kb[(size_t)NB * LK * KW];
__device__ u32 d_vb[(size_t)NB * LK * VW];
__device__ u32 d_qb[(size_t)NB * LQ * QW];
__device__ float d_po[(size_t)NSPLIT * NB * LQ * DIN]; // partial o sums
__device__ float d_pl[(size_t)NSPLIT * NB * LQ];       // partial l sums

// pack two f32 -> f16x2 (lo = first arg)
__device__ __forceinline__ u32 pack_f16(float lo, float hi) {
    u32 d; asm("cvt.rn.f16x2.f32 %0, %1, %2;" : "=r"(d) : "f"(hi), "f"(lo));
    return d;
}
// dual exp2 on packed f16x2
__device__ __forceinline__ u32 ex2h2(u32 a) {
    u32 d; asm("ex2.approx.f16x2 %0, %1;" : "=r"(d) : "r"(a));
    return d;
}
// m16n8k16 f16 mma: D = A*B + C (fp32 accum)
__device__ __forceinline__ void mma_f16(
    float& d0, float& d1, float& d2, float& d3,
    u32 a0, u32 a1, u32 a2, u32 a3, u32 b0, u32 b1,
    float c0, float c1, float c2, float c3)
{
    asm("mma.sync.aligned.m16n8k16.row.col.f32.f16.f16.f32 "
        "{%0,%1,%2,%3},{%4,%5,%6,%7},{%8,%9},{%10,%11,%12,%13};"
        : "=f"(d0), "=f"(d1), "=f"(d2), "=f"(d3)
        : "r"(a0), "r"(a1), "r"(a2), "r"(a3), "r"(b0), "r"(b1),
          "f"(c0), "f"(c1), "f"(c2), "f"(c3));
}
__device__ __forceinline__ void cp16(u32 dst, const void* src) {
    asm volatile("cp.async.cg.shared.global [%0], [%1], 16;" :: "r"(dst), "l"(src));
}
#define CP_COMMIT() asm volatile("cp.async.commit_group;")
#define CP_WAIT0()  asm volatile("cp.async.wait_group 0;")

// ---------------------------------------------------------------------------
// Kernel 1: projections -> f16, split 3 ways by blockIdx.y (0=V, 1=K, 2=Q).
// K rows carry the mask bias at feature 20 (Q has 1.0 there).
// V rows carry a ones-column at dim 32 (softmax denominator via tensor pipe).
// ---------------------------------------------------------------------------
__global__ __launch_bounds__(256) void proj_kernel(
    const float* __restrict__ vals, const float* __restrict__ keys,
    const float* __restrict__ ques, const void* __restrict__ mask_raw,
    const float* __restrict__ Wv, const float* __restrict__ Wk, const float* __restrict__ Wq,
    const float* __restrict__ gk, const float* __restrict__ bk,
    const float* __restrict__ gq, const float* __restrict__ bq)
{
    __shared__ float sW[DIN * DIN];
    __shared__ float sg[DKQ], sb[DKQ];
    __shared__ int s_is_byte;

    int tid  = threadIdx.x;
    int task = blockIdx.y;
    size_t r = (size_t)blockIdx.x * 256 + tid;

    if (task == 0) {
        for (int i = tid; i < DIN * DIN; i += 256) sW[i] = Wv[i];
        __syncthreads();

        float x[DIN];
        const float4* p4 = (const float4*)(vals + r * DIN);
        #pragma unroll
        for (int i = 0; i < 8; i++) {
            float4 t = p4[i];
            x[4*i] = t.x; x[4*i+1] = t.y; x[4*i+2] = t.z; x[4*i+3] = t.w;
        }
        float outr[DIN];
        #pragma unroll
        for (int o = 0; o < DIN; o++) {
            float acc = 0.f;
            #pragma unroll
            for (int d = 0; d < DIN; d++) acc += x[d] * sW[o * DIN + d];
            outr[o] = acc;
        }
        u32 wv[VW];
        #pragma unroll
        for (int p = 0; p < 16; p++) wv[p] = pack_f16(outr[2*p], outr[2*p+1]);
        wv[16] = pack_f16(1.0f, 0.f);      // ones-column @ dim 32
        #pragma unroll
        for (int p = 17; p < VW; p++) wv[p] = 0u;
        uint4* o4 = (uint4*)(d_vb + r * VW);
        #pragma unroll
        for (int i = 0; i < 5; i++)
            o4[i] = make_uint4(wv[4*i], wv[4*i+1], wv[4*i+2], wv[4*i+3]);
    } else {
        const float* W  = (task == 1) ? Wk : Wq;
        const float* gg = (task == 1) ? gk : gq;
        const float* bb = (task == 1) ? bk : bq;
        const float* in = (task == 1) ? keys : ques;
        for (int i = tid; i < DKQ * DIN; i += 256) sW[i] = W[i];
        if (tid < DKQ) { sg[tid] = gg[tid]; sb[tid] = bb[tid]; }
        if (task == 1 && tid == 0) {
            // Detect mask storage: numpy bool (1 byte) vs int32 coercion.
            const unsigned int* wd = (const unsigned int*)mask_raw;
            unsigned int acc = 0;
            for (int k = 0; k < 64; k++) acc |= wd[k] & 0xFFFFFF00u;
            s_is_byte = (acc != 0u);
        }
        __syncthreads();

        float x[DIN];
        const float4* p4 = (const float4*)(in + r * DIN);
        #pragma unroll
        for (int i = 0; i < 8; i++) {
            float4 t = p4[i];
            x[4*i] = t.x; x[4*i+1] = t.y; x[4*i+2] = t.z; x[4*i+3] = t.w;
        }
        float y[DKQ];
        #pragma unroll
        for (int o = 0; o < DKQ; o++) {
            float acc = 0.f;
            #pragma unroll
            for (int d = 0; d < DIN; d++) acc += x[d] * sW[o * DIN + d];
            y[o] = acc;
        }
        float m = 0.f;
        #pragma unroll
        for (int c = 0; c < DKQ; c++) m += y[c];
        m *= (1.f / DKQ);
        float v = 0.f;
        #pragma unroll
        for (int c = 0; c < DKQ; c++) { float d = y[c] - m; v += d * d; }
        v *= (1.f / DKQ);
        float rs = rsqrtf(v + EPS);

        if (task == 1) {
            #pragma unroll
            for (int c = 0; c < DKQ; c++) y[c] = (y[c] - m) * rs * sg[c] + sb[c];
            int mv = s_is_byte ? (int)((const unsigned char*)mask_raw)[r]
                               : ((const int*)mask_raw)[r];
            float bias = mv ? BIAS_MASKED : 0.f;   // True masks OUT
            u32 wv[KW];
            #pragma unroll
            for (int p = 0; p < 10; p++) wv[p] = pack_f16(y[2*p], y[2*p+1]);
            wv[10] = pack_f16(bias, 0.f);
            #pragma unroll
            for (int p = 11; p < KW; p++) wv[p] = 0u;
            uint4* o4 = (uint4*)(d_kb + r * KW);
            #pragma unroll
            for (int i = 0; i < 5; i++)
                o4[i] = make_uint4(wv[4*i], wv[4*i+1], wv[4*i+2], wv[4*i+3]);
        } else {
            #pragma unroll
            for (int c = 0; c < DKQ; c++)
                y[c] = ((y[c] - m) * rs * sg[c] + sb[c]) * QSCALE;
            u32 wv[QW];
            #pragma unroll
            for (int p = 0; p < 10; p++) wv[p] = pack_f16(y[2*p], y[2*p+1]);
            wv[10] = pack_f16(1.0f, 0.f);
            #pragma unroll
            for (int p = 11; p < QW; p++) wv[p] = 0u;
            uint4* o4 = (uint4*)(d_qb + r * QW);
            #pragma unroll
            for (int i = 0; i < 4; i++)
                o4[i] = make_uint4(wv[4*i], wv[4*i+1], wv[4*i+2], wv[4*i+3]);
        }
    }
}

// ---------------------------------------------------------------------------
// Kernel 2: split-K flash attention, f16 m16n8k16 + ldmatrix, cp.async
// double-buffered TS=64 tiles. TWO m16 tiles per warp (K/V frags amortized,
// low L1 traffic) x NSPLIT=2 key-splits (1024 CTAs, high residency).
// grid = (LQ/128, NB, NSPLIT); CTA = 128 thr = 4 warps = 128 queries.
// Emits unnormalized partials (o-sum via PV, l via V ones-column).
// ---------------------------------------------------------------------------
#define TS 64
#define NT (LKH / TS)
#define T16 (TS * KW / 4)   // 320 uint4 per tile (K and V identical)

__global__ __launch_bounds__(128) void attn_partial_kernel()
{
    __shared__ u32 sK[2][TS * KW];   // 2 x 5120 B
    __shared__ u32 sV[2][TS * VW];   // 2 x 5120 B

    int tid  = threadIdx.x;
    int w    = tid >> 5;
    int lane = tid & 31;
    int g    = lane >> 2;   // group id (0..7)
    int i    = lane & 3;    // thread in group (0..3)
    int b    = blockIdx.y;
    int h    = blockIdx.z;
    int qbase = blockIdx.x * 128 + w * 32;

    // ---- Q fragments: two m16 tiles x two k16 chunks, in registers ----
    u32 aq[2][2][4];
    #pragma unroll
    for (int t = 0; t < 2; t++) {
        const u32* q0p = d_qb + ((size_t)b * LQ + qbase + t * 16 + g) * QW;
        const u32* q1p = q0p + 8 * QW;
        #pragma unroll
        for (int c = 0; c < 2; c++) {
            aq[t][c][0] = q0p[8 * c + i];
            aq[t][c][1] = q1p[8 * c + i];
            aq[t][c][2] = q0p[8 * c + i + 4];
            aq[t][c][3] = q1p[8 * c + i + 4];
        }
    }

    // o[t][nt] nt=0..3: output dims; nt=4: ones-column (denominator)
    float o[2][5][4];
    #pragma unroll
    for (int t = 0; t < 2; t++)
        #pragma unroll
        for (int nt = 0; nt < 5; nt++)
            #pragma unroll
            for (int r = 0; r < 4; r++) o[t][nt][r] = 0.f;

    const u32* kgl = d_kb + ((size_t)b * LK + (size_t)h * LKH) * KW;
    const u32* vgl = d_vb + ((size_t)b * LK + (size_t)h * LKH) * VW;

    u32 sK_u[2], sV_u[2];
    sK_u[0] = (u32)__cvta_generic_to_shared(&sK[0][0]);
    sK_u[1] = (u32)__cvta_generic_to_shared(&sK[1][0]);
    sV_u[0] = (u32)__cvta_generic_to_shared(&sV[0][0]);
    sV_u[1] = (u32)__cvta_generic_to_shared(&sV[1][0]);

    // ---- preamble: async load tile 0 ----
    {
        #pragma unroll
        for (int rr = 0; rr < 3; rr++) {
            int idx = tid + rr * 128;
            if (idx < T16) {
                cp16(sK_u[0] + idx * 16, kgl + idx * 4);
                cp16(sV_u[0] + idx * 16, vgl + idx * 4);
            }
        }
        CP_COMMIT();
    }

    for (int t0 = 0; t0 < NT; t0++) {
        int cur = t0 & 1;
        CP_WAIT0();
        __syncthreads();   // tile t0 ready; all warps done with buffer we refill

        // prefetch tile t0+1 (overlaps with compute below)
        if (t0 + 1 < NT) {
            int nxt = cur ^ 1;
            const u32* kg2 = kgl + (size_t)(t0 + 1) * TS * KW;
            const u32* vg2 = vgl + (size_t)(t0 + 1) * TS * VW;
            #pragma unroll
            for (int rr = 0; rr < 3; rr++) {
                int idx = tid + rr * 128;
                if (idx < T16) {
                    cp16(sK_u[nxt] + idx * 16, kg2 + idx * 4);
                    cp16(sV_u[nxt] + idx * 16, vg2 + idx * 4);
                }
            }
            CP_COMMIT();
        }

        #pragma unroll
        for (int kg = 0; kg < TS / 16; kg++) {
            // ---- K fragments: 8-key groups A (keys kg*16+0..7) and B (+8..15)
            const u32* kA = &sK[cur][(kg * 16 + g) * KW];
            const u32* kB = kA + 8 * KW;
            u32 kbA[4], kbB[4];
            kbA[0] = kA[i];     kbA[1] = kA[i + 4];
            kbA[2] = kA[8 + i]; kbA[3] = kA[12 + i];
            kbB[0] = kB[i];     kbB[1] = kB[i + 4];
            kbB[2] = kB[8 + i]; kbB[3] = kB[12 + i];

            // ---- V fragments: ldmatrix x4 (dims 0..31) + x2 (ones col 32..39)
            u32 vb0[4], vb1[4], vb40, vb41;
            {
                int rrow = lane & 7, mm = lane >> 3;
                u32 a1 = sV_u[cur] + ((kg * 16 + rrow) * VW + mm * 4) * 4;
                u32 a2 = a1 + 8 * VW * 4;
                asm volatile("ldmatrix.sync.aligned.m8n8.x4.trans.shared.b16 "
                             "{%0,%1,%2,%3}, [%4];"
                    : "=r"(vb0[0]), "=r"(vb0[1]), "=r"(vb0[2]), "=r"(vb0[3]) : "r"(a1));
                asm volatile("ldmatrix.sync.aligned.m8n8.x4.trans.shared.b16 "
                             "{%0,%1,%2,%3}, [%4];"
                    : "=r"(vb1[0]), "=r"(vb1[1]), "=r"(vb1[2]), "=r"(vb1[3]) : "r"(a2));
                u32 a3 = sV_u[cur] +
                    ((kg * 16 + (lane & 7) + ((lane >> 3) & 1) * 8) * VW + 16) * 4;
                asm volatile("ldmatrix.sync.aligned.m8n8.x2.trans.shared.b16 "
                             "{%0,%1}, [%2];"
                    : "=r"(vb40), "=r"(vb41) : "r"(a3));
            }

            // two independent M-tiles share the K/V fragments
            #pragma unroll
            for (int t = 0; t < 2; t++) {
                float sA0 = 0.f, sA1 = 0.f, sA2 = 0.f, sA3 = 0.f;
                float sB0 = 0.f, sB1 = 0.f, sB2 = 0.f, sB3 = 0.f;
                mma_f16(sA0, sA1, sA2, sA3,
                        aq[t][0][0], aq[t][0][1], aq[t][0][2], aq[t][0][3],
                        kbA[0], kbA[1], sA0, sA1, sA2, sA3);
                mma_f16(sA0, sA1, sA2, sA3,
                        aq[t][1][0], aq[t][1][1], aq[t][1][2], aq[t][1][3],
                        kbA[2], kbA[3], sA0, sA1, sA2, sA3);
                mma_f16(sB0, sB1, sB2, sB3,
                        aq[t][0][0], aq[t][0][1], aq[t][0][2], aq[t][0][3],
                        kbB[0], kbB[1], sB0, sB1, sB2, sB3);
                mma_f16(sB0, sB1, sB2, sB3,
                        aq[t][1][0], aq[t][1][1], aq[t][1][2], aq[t][1][3],
                        kbB[2], kbB[3], sB0, sB1, sB2, sB3);

                // pack score pairs -> f16x2, dual-exp via one MUFU op each.
                u32 pa0 = ex2h2(pack_f16(sA0, sA1));   // row g,   keys 2i,2i+1
                u32 pa1 = ex2h2(pack_f16(sA2, sA3));   // row g+8
                u32 pa2 = ex2h2(pack_f16(sB0, sB1));   // row g,   keys 8+2i..
                u32 pa3 = ex2h2(pack_f16(sB2, sB3));   // row g+8

                #pragma unroll
                for (int nt = 0; nt < 4; nt++) {
                    mma_f16(o[t][nt][0], o[t][nt][1], o[t][nt][2], o[t][nt][3],
                            pa0, pa1, pa2, pa3, vb0[nt], vb1[nt],
                            o[t][nt][0], o[t][nt][1], o[t][nt][2], o[t][nt][3]);
                }
                // ones-column: accumulates softmax denominator per row
                mma_f16(o[t][4][0], o[t][4][1], o[t][4][2], o[t][4][3],
                        pa0, pa1, pa2, pa3, vb40, vb41,
                        o[t][4][0], o[t][4][1], o[t][4][2], o[t][4][3]);
            }
        }
    }

    // ---- store partials (unnormalized o-sum and l-sum) ----
    size_t pbase = ((size_t)h * NB + b) * LQ;
    #pragma unroll
    for (int t = 0; t < 2; t++) {
        #pragma unroll
        for (int half = 0; half < 2; half++) {
            int row = qbase + t * 16 + g + half * 8;
            int r0  = half == 0 ? 0 : 2;
            float2* po = (float2*)(d_po + (pbase + row) * DIN);
            #pragma unroll
            for (int nt = 0; nt < 4; nt++) {
                float2 tt;
                tt.x = o[t][nt][r0];
                tt.y = o[t][nt][r0 + 1];
                po[nt * 4 + i] = tt;
            }
            // l lives in ones-column accumulator, valid at i==0 lanes
            if (i == 0) d_pl[pbase + row] = o[t][4][r0];
        }
    }
}

// ---------------------------------------------------------------------------
// Kernel 3: combine partials + residual + final LayerNorm. One thread per row.
// ---------------------------------------------------------------------------
__global__ __launch_bounds__(256) void combine_kernel(
    const float* __restrict__ ques,
    const float* __restrict__ go, const float* __restrict__ bo,
    float* __restrict__ out)
{
    __shared__ float sgo[DIN], sbo[DIN];
    int tid = threadIdx.x;
    if (tid < DIN) { sgo[tid] = go[tid]; sbo[tid] = bo[tid]; }
    __syncthreads();

    size_t r = (size_t)blockIdx.x * 256 + tid;          // row in [0, NB*LQ)
    const size_t half = (size_t)NB * LQ;

    float l = d_pl[r] + d_pl[half + r];
    float invl = 1.f / l;

    const float4* a4 = (const float4*)(d_po + r * DIN);
    const float4* b4 = (const float4*)(d_po + (half + r) * DIN);
    const float4* q4 = (const float4*)(ques + r * DIN);

    float tv[DIN];
    #pragma unroll
    for (int i = 0; i < 8; i++) {
        float4 a = a4[i], b = b4[i], q = q4[i];
        tv[4*i]   = (a.x + b.x) * invl + q.x;
        tv[4*i+1] = (a.y + b.y) * invl + q.y;
        tv[4*i+2] = (a.z + b.z) * invl + q.z;
        tv[4*i+3] = (a.w + b.w) * invl + q.w;
    }

    float m = 0.f;
    #pragma unroll
    for (int c = 0; c < DIN; c++) m += tv[c];
    m *= (1.f / DIN);
    float v = 0.f;
    #pragma unroll
    for (int c = 0; c < DIN; c++) { float d = tv[c] - m; v += d * d; }
    v *= (1.f / DIN);
    float rs = rsqrtf(v + EPS);

    float4* po = (float4*)(out + r * DIN);
    #pragma unroll
    for (int i = 0; i < 8; i++) {
        float4 t;
        t.x = (tv[4*i]   - m) * rs * sgo[4*i]   + sbo[4*i];
        t.y = (tv[4*i+1] - m) * rs * sgo[4*i+1] + sbo[4*i+1];
        t.z = (tv[4*i+2] - m) * rs * sgo[4*i+2] + sbo[4*i+2];
        t.w = (tv[4*i+3] - m) * rs * sgo[4*i+3] + sbo[4*i+3];
        po[i] = t;
    }
}

// ---------------------------------------------------------------------------
extern "C" void kernel_launch(void* const* d_in, const int* in_sizes, int n_in,
                              void* d_out, int out_size)
{
    const float* vals = (const float*)d_in[0];
    const float* keys = (const float*)d_in[1];
    const float* ques = (const float*)d_in[2];
    const void*  mask = d_in[3];
    const float* Wv   = (const float*)d_in[4];
    const float* Wk   = (const float*)d_in[5];
    const float* Wq   = (const float*)d_in[6];
    const float* gk   = (const float*)d_in[7];
    const float* bk   = (const float*)d_in[8];
    const float* gq   = (const float*)d_in[9];
    const float* bq   = (const float*)d_in[10];
    const float* go   = (const float*)d_in[11];
    const float* bo   = (const float*)d_in[12];
    float* out = (float*)d_out;

    dim3 pgrid((NB * LK) / 256, 3);
    proj_kernel<<<pgrid, 256>>>(vals, keys, ques, mask, Wv, Wk, Wq, gk, bk, gq, bq);

    dim3 grid(LQ / 128, NB, NSPLIT);
    attn_partial_kernel<<<grid, 128>>>();

    combine_kernel<<<(NB * LQ) / 256, 256>>>(ques, go, bo, out);
}

// round 13
// speedup vs baseline: 1.0571x; 1.0571x over previous
#include <cuda_runtime.h>
#include <cstdint>

// Problem constants
#define NB   32
#define LQ   2048
#define LK   2048
#define DIN  32
#define DKQ  20
#define EPS  1e-5f
// fold 1/sqrt(20) * log2(e) into q so scores are in log2 domain
#define QSCALE 0.32258572299984063f   // log2(e)/sqrt(20)
#define BIAS_MASKED (-60000.0f)       // f16-finite; ex2 -> exactly 0

// f16 storage strides (in u32 words = f16 pairs)
#define KW 20   // K row: feats 0..19, bias@20, zero-pad to 40 f16 -> 80B
#define VW 20   // V row: dims 0..31, ones-col@32, zero-pad to 40 f16 -> 80B
#define QW 16   // Q row: feats 0..19, 1.0@20, zero-pad to 32 f16 -> 64B

typedef unsigned int u32;

// Scratch (allocation-free rule: __device__ globals), f16 pairs as u32
__device__ u32 d_kb[(size_t)NB * LK * KW];
__device__ u32 d_vb[(size_t)NB * LK * VW];
__device__ u32 d_qb[(size_t)NB * LQ * QW];

// pack two f32 -> f16x2 (lo = first arg)
__device__ __forceinline__ u32 pack_f16(float lo, float hi) {
    u32 d; asm("cvt.rn.f16x2.f32 %0, %1, %2;" : "=r"(d) : "f"(hi), "f"(lo));
    return d;
}
// dual exp2 on packed f16x2
__device__ __forceinline__ u32 ex2h2(u32 a) {
    u32 d; asm("ex2.approx.f16x2 %0, %1;" : "=r"(d) : "r"(a));
    return d;
}
// m16n8k16 f16 mma: D = A*B + C (fp32 accum)
__device__ __forceinline__ void mma_f16(
    float& d0, float& d1, float& d2, float& d3,
    u32 a0, u32 a1, u32 a2, u32 a3, u32 b0, u32 b1,
    float c0, float c1, float c2, float c3)
{
    asm("mma.sync.aligned.m16n8k16.row.col.f32.f16.f16.f32 "
        "{%0,%1,%2,%3},{%4,%5,%6,%7},{%8,%9},{%10,%11,%12,%13};"
        : "=f"(d0), "=f"(d1), "=f"(d2), "=f"(d3)
        : "r"(a0), "r"(a1), "r"(a2), "r"(a3), "r"(b0), "r"(b1),
          "f"(c0), "f"(c1), "f"(c2), "f"(c3));
}
__device__ __forceinline__ void cp16(u32 dst, const void* src) {
    asm volatile("cp.async.cg.shared.global [%0], [%1], 16;" :: "r"(dst), "l"(src));
}
#define CP_COMMIT() asm volatile("cp.async.commit_group;")
#define CP_WAIT0()  asm volatile("cp.async.wait_group 0;")

__device__ __forceinline__ float dot4(float4 a, float4 b, float acc) {
    acc = fmaf(a.x, b.x, acc);
    acc = fmaf(a.y, b.y, acc);
    acc = fmaf(a.z, b.z, acc);
    acc = fmaf(a.w, b.w, acc);
    return acc;
}

// ---------------------------------------------------------------------------
// Kernel 1: projections -> f16, split 3 ways by blockIdx.y (0=V, 1=K, 2=Q).
// Weights read via float4 (forces LDS.128, 4x fewer smem instructions).
// V outputs computed in two 16-wide chunks to cap register pressure.
// ---------------------------------------------------------------------------
__global__ __launch_bounds__(256) void proj_kernel(
    const float* __restrict__ vals, const float* __restrict__ keys,
    const float* __restrict__ ques, const void* __restrict__ mask_raw,
    const float* __restrict__ Wv, const float* __restrict__ Wk, const float* __restrict__ Wq,
    const float* __restrict__ gk, const float* __restrict__ bk,
    const float* __restrict__ gq, const float* __restrict__ bq)
{
    __shared__ float sW[DIN * DIN];
    __shared__ float sg[DKQ], sb[DKQ];
    __shared__ int s_is_byte;

    int tid  = threadIdx.x;
    int task = blockIdx.y;
    size_t r = (size_t)blockIdx.x * 256 + tid;

    if (task == 0) {
        for (int i = tid; i < DIN * DIN; i += 256) sW[i] = Wv[i];
        __syncthreads();

        float4 xa[8];
        const float4* p4 = (const float4*)(vals + r * DIN);
        #pragma unroll
        for (int i = 0; i < 8; i++) xa[i] = p4[i];

        uint4* o4 = (uint4*)(d_vb + r * VW);
        // two 16-output chunks keep live registers low
        #pragma unroll
        for (int half = 0; half < 2; half++) {
            float outr[16];
            #pragma unroll
            for (int o = 0; o < 16; o++) {
                const float4* wr = (const float4*)(sW + (half * 16 + o) * DIN);
                float acc = 0.f;
                #pragma unroll
                for (int d = 0; d < 8; d++) acc = dot4(xa[d], wr[d], acc);
                outr[o] = acc;
            }
            u32 wv[8];
            #pragma unroll
            for (int p = 0; p < 8; p++) wv[p] = pack_f16(outr[2*p], outr[2*p+1]);
            o4[half * 2]     = make_uint4(wv[0], wv[1], wv[2], wv[3]);
            o4[half * 2 + 1] = make_uint4(wv[4], wv[5], wv[6], wv[7]);
        }
        o4[4] = make_uint4(pack_f16(1.0f, 0.f), 0u, 0u, 0u);  // ones-col @ dim 32
    } else {
        const float* W  = (task == 1) ? Wk : Wq;
        const float* gg = (task == 1) ? gk : gq;
        const float* bb = (task == 1) ? bk : bq;
        const float* in = (task == 1) ? keys : ques;
        for (int i = tid; i < DKQ * DIN; i += 256) sW[i] = W[i];
        if (tid < DKQ) { sg[tid] = gg[tid]; sb[tid] = bb[tid]; }
        if (task == 1 && tid == 0) {
            // Detect mask storage: numpy bool (1 byte) vs int32 coercion.
            const unsigned int* wd = (const unsigned int*)mask_raw;
            unsigned int acc = 0;
            for (int k = 0; k < 64; k++) acc |= wd[k] & 0xFFFFFF00u;
            s_is_byte = (acc != 0u);
        }
        __syncthreads();

        float4 xa[8];
        const float4* p4 = (const float4*)(in + r * DIN);
        #pragma unroll
        for (int i = 0; i < 8; i++) xa[i] = p4[i];

        float y[DKQ];
        #pragma unroll
        for (int o = 0; o < DKQ; o++) {
            const float4* wr = (const float4*)(sW + o * DIN);
            float acc = 0.f;
            #pragma unroll
            for (int d = 0; d < 8; d++) acc = dot4(xa[d], wr[d], acc);
            y[o] = acc;
        }
        float m = 0.f;
        #pragma unroll
        for (int c = 0; c < DKQ; c++) m += y[c];
        m *= (1.f / DKQ);
        float v = 0.f;
        #pragma unroll
        for (int c = 0; c < DKQ; c++) { float d = y[c] - m; v += d * d; }
        v *= (1.f / DKQ);
        float rs = rsqrtf(v + EPS);

        if (task == 1) {
            #pragma unroll
            for (int c = 0; c < DKQ; c++) y[c] = (y[c] - m) * rs * sg[c] + sb[c];
            int mv = s_is_byte ? (int)((const unsigned char*)mask_raw)[r]
                               : ((const int*)mask_raw)[r];
            float bias = mv ? BIAS_MASKED : 0.f;   // True masks OUT
            u32 wv[KW];
            #pragma unroll
            for (int p = 0; p < 10; p++) wv[p] = pack_f16(y[2*p], y[2*p+1]);
            wv[10] = pack_f16(bias, 0.f);
            #pragma unroll
            for (int p = 11; p < KW; p++) wv[p] = 0u;
            uint4* o4 = (uint4*)(d_kb + r * KW);
            #pragma unroll
            for (int i = 0; i < 5; i++)
                o4[i] = make_uint4(wv[4*i], wv[4*i+1], wv[4*i+2], wv[4*i+3]);
        } else {
            #pragma unroll
            for (int c = 0; c < DKQ; c++)
                y[c] = ((y[c] - m) * rs * sg[c] + sb[c]) * QSCALE;
            u32 wv[QW];
            #pragma unroll
            for (int p = 0; p < 10; p++) wv[p] = pack_f16(y[2*p], y[2*p+1]);
            wv[10] = pack_f16(1.0f, 0.f);
            #pragma unroll
            for (int p = 11; p < QW; p++) wv[p] = 0u;
            uint4* o4 = (uint4*)(d_qb + r * QW);
            #pragma unroll
            for (int i = 0; i < 4; i++)
                o4[i] = make_uint4(wv[4*i], wv[4*i+1], wv[4*i+2], wv[4*i+3]);
        }
    }
}

// ---------------------------------------------------------------------------
// Kernel 2: flash attention, f16 m16n8k16 mma + ldmatrix, cp.async
// double-buffered TS=64 tiles. ONE m16 tile (16 queries) per warp:
// CTA = 128 thr = 4 warps = 64 queries; grid = (LQ/64, NB) = 1024 CTAs.
// exp via ex2.approx.f16x2; denominator via V ones-column. (R11 structure.)
// ---------------------------------------------------------------------------
#define TS 64
#define NT (LK / TS)
#define T16 (TS * KW / 4)   // 320 uint4 per tile (K and V identical)

__global__ __launch_bounds__(128) void attn_kernel(
    const float* __restrict__ ques,
    const float* __restrict__ go, const float* __restrict__ bo,
    float* __restrict__ out)
{
    __shared__ u32 sK[2][TS * KW];   // 2 x 5120 B
    __shared__ u32 sV[2][TS * VW];   // 2 x 5120 B

    int tid  = threadIdx.x;
    int w    = tid >> 5;
    int lane = tid & 31;
    int g    = lane >> 2;   // group id (0..7)
    int i    = lane & 3;    // thread in group (0..3)
    int b    = blockIdx.y;
    int qbase = blockIdx.x * 64 + w * 16;

    // ---- Q fragments: one m16 tile x two k16 chunks, in registers ----
    u32 aq[2][4];
    {
        const u32* q0p = d_qb + ((size_t)b * LQ + qbase + g) * QW;
        const u32* q1p = q0p + 8 * QW;
        #pragma unroll
        for (int c = 0; c < 2; c++) {
            aq[c][0] = q0p[8 * c + i];
            aq[c][1] = q1p[8 * c + i];
            aq[c][2] = q0p[8 * c + i + 4];
            aq[c][3] = q1p[8 * c + i + 4];
        }
    }

    // o[nt] nt=0..3: output dims; nt=4: ones-column (denominator)
    float o[5][4];
    #pragma unroll
    for (int nt = 0; nt < 5; nt++)
        #pragma unroll
        for (int r = 0; r < 4; r++) o[nt][r] = 0.f;

    const u32* kgl = d_kb + (size_t)b * LK * KW;
    const u32* vgl = d_vb + (size_t)b * LK * VW;

    u32 sK_u[2], sV_u[2];
    sK_u[0] = (u32)__cvta_generic_to_shared(&sK[0][0]);
    sK_u[1] = (u32)__cvta_generic_to_shared(&sK[1][0]);
    sV_u[0] = (u32)__cvta_generic_to_shared(&sV[0][0]);
    sV_u[1] = (u32)__cvta_generic_to_shared(&sV[1][0]);

    // ---- preamble: async load tile 0 ----
    {
        #pragma unroll
        for (int rr = 0; rr < 3; rr++) {
            int idx = tid + rr * 128;
            if (idx < T16) {
                cp16(sK_u[0] + idx * 16, kgl + idx * 4);
                cp16(sV_u[0] + idx * 16, vgl + idx * 4);
            }
        }
        CP_COMMIT();
    }

    for (int t0 = 0; t0 < NT; t0++) {
        int cur = t0 & 1;
        CP_WAIT0();
        __syncthreads();   // tile t0 ready; all warps done with buffer we refill

        // prefetch tile t0+1 (overlaps with compute below)
        if (t0 + 1 < NT) {
            int nxt = cur ^ 1;
            const u32* kg2 = kgl + (size_t)(t0 + 1) * TS * KW;
            const u32* vg2 = vgl + (size_t)(t0 + 1) * TS * VW;
            #pragma unroll
            for (int rr = 0; rr < 3; rr++) {
                int idx = tid + rr * 128;
                if (idx < T16) {
                    cp16(sK_u[nxt] + idx * 16, kg2 + idx * 4);
                    cp16(sV_u[nxt] + idx * 16, vg2 + idx * 4);
                }
            }
            CP_COMMIT();
        }

        #pragma unroll
        for (int kg = 0; kg < TS / 16; kg++) {
            // ---- K fragments: 8-key groups A (keys kg*16+0..7) and B (+8..15)
            const u32* kA = &sK[cur][(kg * 16 + g) * KW];
            const u32* kB = kA + 8 * KW;
            u32 kbA[4], kbB[4];
            kbA[0] = kA[i];     kbA[1] = kA[i + 4];
            kbA[2] = kA[8 + i]; kbA[3] = kA[12 + i];
            kbB[0] = kB[i];     kbB[1] = kB[i + 4];
            kbB[2] = kB[8 + i]; kbB[3] = kB[12 + i];

            // ---- V fragments: ldmatrix x4 (dims 0..31) + x2 (ones col 32..39)
            u32 vb0[4], vb1[4], vb40, vb41;
            {
                int rrow = lane & 7, mm = lane >> 3;
                u32 a1 = sV_u[cur] + ((kg * 16 + rrow) * VW + mm * 4) * 4;
                u32 a2 = a1 + 8 * VW * 4;
                asm volatile("ldmatrix.sync.aligned.m8n8.x4.trans.shared.b16 "
                             "{%0,%1,%2,%3}, [%4];"
                    : "=r"(vb0[0]), "=r"(vb0[1]), "=r"(vb0[2]), "=r"(vb0[3]) : "r"(a1));
                asm volatile("ldmatrix.sync.aligned.m8n8.x4.trans.shared.b16 "
                             "{%0,%1,%2,%3}, [%4];"
                    : "=r"(vb1[0]), "=r"(vb1[1]), "=r"(vb1[2]), "=r"(vb1[3]) : "r"(a2));
                u32 a3 = sV_u[cur] +
                    ((kg * 16 + (lane & 7) + ((lane >> 3) & 1) * 8) * VW + 16) * 4;
                asm volatile("ldmatrix.sync.aligned.m8n8.x2.trans.shared.b16 "
                             "{%0,%1}, [%2];"
                    : "=r"(vb40), "=r"(vb41) : "r"(a3));
            }

            // QK^T for both 8-key groups (bias included via K[20])
            float sA0 = 0.f, sA1 = 0.f, sA2 = 0.f, sA3 = 0.f;
            float sB0 = 0.f, sB1 = 0.f, sB2 = 0.f, sB3 = 0.f;
            mma_f16(sA0, sA1, sA2, sA3,
                    aq[0][0], aq[0][1], aq[0][2], aq[0][3],
                    kbA[0], kbA[1], sA0, sA1, sA2, sA3);
            mma_f16(sA0, sA1, sA2, sA3,
                    aq[1][0], aq[1][1], aq[1][2], aq[1][3],
                    kbA[2], kbA[3], sA0, sA1, sA2, sA3);
            mma_f16(sB0, sB1, sB2, sB3,
                    aq[0][0], aq[0][1], aq[0][2], aq[0][3],
                    kbB[0], kbB[1], sB0, sB1, sB2, sB3);
            mma_f16(sB0, sB1, sB2, sB3,
                    aq[1][0], aq[1][1], aq[1][2], aq[1][3],
                    kbB[2], kbB[3], sB0, sB1, sB2, sB3);

            // pack score pairs -> f16x2, dual-exp via one MUFU op each.
            // Resulting f16x2 IS the P A-fragment (no further packing).
            u32 pa0 = ex2h2(pack_f16(sA0, sA1));   // row g,   keys 2i,2i+1
            u32 pa1 = ex2h2(pack_f16(sA2, sA3));   // row g+8
            u32 pa2 = ex2h2(pack_f16(sB0, sB1));   // row g,   keys 8+2i..
            u32 pa3 = ex2h2(pack_f16(sB2, sB3));   // row g+8

            #pragma unroll
            for (int nt = 0; nt < 4; nt++) {
                mma_f16(o[nt][0], o[nt][1], o[nt][2], o[nt][3],
                        pa0, pa1, pa2, pa3, vb0[nt], vb1[nt],
                        o[nt][0], o[nt][1], o[nt][2], o[nt][3]);
            }
            // ones-column: accumulates softmax denominator per row
            mma_f16(o[4][0], o[4][1], o[4][2], o[4][3],
                    pa0, pa1, pa2, pa3, vb40, vb41,
                    o[4][0], o[4][1], o[4][2], o[4][3]);
        }
    }

    // ---- epilogue: broadcast l (ones-col, i==0 lanes), normalize, residual,
    //      LayerNorm, store ----
    {
        // l lives at col 32 -> local col 0 -> lanes with i==0
        float l0 = __shfl_sync(0xFFFFFFFFu, o[4][0], lane & 28);  // row g
        float l1 = __shfl_sync(0xFFFFFFFFu, o[4][2], lane & 28);  // row g+8
        float inv0 = 1.f / l0;
        float inv1 = 1.f / l1;

        #pragma unroll
        for (int half = 0; half < 2; half++) {
            int   row  = qbase + g + half * 8;
            float invl = half == 0 ? inv0 : inv1;
            int   r0   = half == 0 ? 0 : 2;

            const float2* qr = (const float2*)(ques + ((size_t)b * LQ + row) * DIN);
            float x[4][2];
            float ssum = 0.f;
            #pragma unroll
            for (int nt = 0; nt < 4; nt++) {
                float2 qv = qr[nt * 4 + i];
                x[nt][0] = o[nt][r0]     * invl + qv.x;
                x[nt][1] = o[nt][r0 + 1] * invl + qv.y;
                ssum += x[nt][0] + x[nt][1];
            }
            ssum += __shfl_xor_sync(0xFFFFFFFFu, ssum, 1);
            ssum += __shfl_xor_sync(0xFFFFFFFFu, ssum, 2);
            float m = ssum * (1.f / DIN);
            float v = 0.f;
            #pragma unroll
            for (int nt = 0; nt < 4; nt++) {
                float d0 = x[nt][0] - m, d1 = x[nt][1] - m;
                v += d0 * d0 + d1 * d1;
            }
            v += __shfl_xor_sync(0xFFFFFFFFu, v, 1);
            v += __shfl_xor_sync(0xFFFFFFFFu, v, 2);
            float rs = rsqrtf(v * (1.f / DIN) + EPS);

            float2* po = (float2*)(out + ((size_t)b * LQ + row) * DIN);
            #pragma unroll
            for (int nt = 0; nt < 4; nt++) {
                int col = nt * 8 + 2 * i;
                float2 tt;
                tt.x = (x[nt][0] - m) * rs * __ldg(go + col)     + __ldg(bo + col);
                tt.y = (x[nt][1] - m) * rs * __ldg(go + col + 1) + __ldg(bo + col + 1);
                po[nt * 4 + i] = tt;
            }
        }
    }
}

// ---------------------------------------------------------------------------
extern "C" void kernel_launch(void* const* d_in, const int* in_sizes, int n_in,
                              void* d_out, int out_size)
{
    const float* vals = (const float*)d_in[0];
    const float* keys = (const float*)d_in[1];
    const float* ques = (const float*)d_in[2];
    const void*  mask = d_in[3];
    const float* Wv   = (const float*)d_in[4];
    const float* Wk   = (const float*)d_in[5];
    const float* Wq   = (const float*)d_in[6];
    const float* gk   = (const float*)d_in[7];
    const float* bk   = (const float*)d_in[8];
    const float* gq   = (const float*)d_in[9];
    const float* bq   = (const float*)d_in[10];
    const float* go   = (const float*)d_in[11];
    const float* bo   = (const float*)d_in[12];
    float* out = (float*)d_out;

    dim3 pgrid((NB * LK) / 256, 3);
    proj_kernel<<<pgrid, 256>>>(vals, keys, ques, mask, Wv, Wk, Wq, gk, bk, gq, bq);

    dim3 grid(LQ / 64, NB);
    attn_kernel<<<grid, 128>>>(ques, go, bo, out);
}

// round 14
// speedup vs baseline: 1.0862x; 1.0275x over previous
#include <cuda_runtime.h>
#include <cstdint>

// Problem constants
#define NB   32
#define LQ   2048
#define LK   2048
#define DIN  32
#define DKQ  20
#define EPS  1e-5f
// fold 1/sqrt(20) * log2(e) into q so scores are in log2 domain
#define QSCALE 0.32258572299984063f   // log2(e)/sqrt(20)
#define BIAS_MASKED (-60000.0f)       // f16-finite; ex2 -> exactly 0

// f16 storage strides (in u32 words = f16 pairs)
#define KWS 12  // K row (global AND smem): feats 0..19 (w0-9), bias@w10, zero w11 -> 48B
#define VWG 16  // V row global: dims 0..31 compact -> 64B
#define VW  20  // V row smem: 16 data words + ones@w16 + zero w17-19 -> 80B (conflict-free ldmatrix)
#define QW  16  // Q row: feats 0..19, 1.0@20, zero-pad to 32 f16 -> 64B

typedef unsigned int u32;

// Scratch (allocation-free rule: __device__ globals), f16 pairs as u32
__device__ u32 d_kb[(size_t)NB * LK * KWS];
__device__ u32 d_vb[(size_t)NB * LK * VWG];
__device__ u32 d_qb[(size_t)NB * LQ * QW];

// pack two f32 -> f16x2 (lo = first arg)
__device__ __forceinline__ u32 pack_f16(float lo, float hi) {
    u32 d; asm("cvt.rn.f16x2.f32 %0, %1, %2;" : "=r"(d) : "f"(hi), "f"(lo));
    return d;
}
// dual exp2 on packed f16x2
__device__ __forceinline__ u32 ex2h2(u32 a) {
    u32 d; asm("ex2.approx.f16x2 %0, %1;" : "=r"(d) : "r"(a));
    return d;
}
// m16n8k16 f16 mma: D = A*B + C (fp32 accum)
__device__ __forceinline__ void mma_f16(
    float& d0, float& d1, float& d2, float& d3,
    u32 a0, u32 a1, u32 a2, u32 a3, u32 b0, u32 b1,
    float c0, float c1, float c2, float c3)
{
    asm("mma.sync.aligned.m16n8k16.row.col.f32.f16.f16.f32 "
        "{%0,%1,%2,%3},{%4,%5,%6,%7},{%8,%9},{%10,%11,%12,%13};"
        : "=f"(d0), "=f"(d1), "=f"(d2), "=f"(d3)
        : "r"(a0), "r"(a1), "r"(a2), "r"(a3), "r"(b0), "r"(b1),
          "f"(c0), "f"(c1), "f"(c2), "f"(c3));
}
__device__ __forceinline__ void cp16(u32 dst, const void* src) {
    asm volatile("cp.async.cg.shared.global [%0], [%1], 16;" :: "r"(dst), "l"(src));
}
#define CP_COMMIT() asm volatile("cp.async.commit_group;")
#define CP_WAIT0()  asm volatile("cp.async.wait_group 0;")

__device__ __forceinline__ float dot4(float4 a, float4 b, float acc) {
    acc = fmaf(a.x, b.x, acc);
    acc = fmaf(a.y, b.y, acc);
    acc = fmaf(a.z, b.z, acc);
    acc = fmaf(a.w, b.w, acc);
    return acc;
}

// ---------------------------------------------------------------------------
// Kernel 1: projections -> f16 (compact layouts), split by blockIdx.y.
// K rows: 12 words (feats + mask bias@10 + 1 pad). V rows: 16 words compact.
// ---------------------------------------------------------------------------
__global__ __launch_bounds__(256) void proj_kernel(
    const float* __restrict__ vals, const float* __restrict__ keys,
    const float* __restrict__ ques, const void* __restrict__ mask_raw,
    const float* __restrict__ Wv, const float* __restrict__ Wk, const float* __restrict__ Wq,
    const float* __restrict__ gk, const float* __restrict__ bk,
    const float* __restrict__ gq, const float* __restrict__ bq)
{
    __shared__ float sW[DIN * DIN];
    __shared__ float sg[DKQ], sb[DKQ];
    __shared__ int s_is_byte;

    int tid  = threadIdx.x;
    int task = blockIdx.y;
    size_t r = (size_t)blockIdx.x * 256 + tid;

    if (task == 0) {
        for (int i = tid; i < DIN * DIN; i += 256) sW[i] = Wv[i];
        __syncthreads();

        float4 xa[8];
        const float4* p4 = (const float4*)(vals + r * DIN);
        #pragma unroll
        for (int i = 0; i < 8; i++) xa[i] = p4[i];

        uint4* o4 = (uint4*)(d_vb + r * VWG);
        // two 16-output chunks keep live registers low
        #pragma unroll
        for (int half = 0; half < 2; half++) {
            float outr[16];
            #pragma unroll
            for (int o = 0; o < 16; o++) {
                const float4* wr = (const float4*)(sW + (half * 16 + o) * DIN);
                float acc = 0.f;
                #pragma unroll
                for (int d = 0; d < 8; d++) acc = dot4(xa[d], wr[d], acc);
                outr[o] = acc;
            }
            u32 wv[8];
            #pragma unroll
            for (int p = 0; p < 8; p++) wv[p] = pack_f16(outr[2*p], outr[2*p+1]);
            o4[half * 2]     = make_uint4(wv[0], wv[1], wv[2], wv[3]);
            o4[half * 2 + 1] = make_uint4(wv[4], wv[5], wv[6], wv[7]);
        }
    } else {
        const float* W  = (task == 1) ? Wk : Wq;
        const float* gg = (task == 1) ? gk : gq;
        const float* bb = (task == 1) ? bk : bq;
        const float* in = (task == 1) ? keys : ques;
        for (int i = tid; i < DKQ * DIN; i += 256) sW[i] = W[i];
        if (tid < DKQ) { sg[tid] = gg[tid]; sb[tid] = bb[tid]; }
        if (task == 1 && tid == 0) {
            // Detect mask storage: numpy bool (1 byte) vs int32 coercion.
            const unsigned int* wd = (const unsigned int*)mask_raw;
            unsigned int acc = 0;
            for (int k = 0; k < 64; k++) acc |= wd[k] & 0xFFFFFF00u;
            s_is_byte = (acc != 0u);
        }
        __syncthreads();

        float4 xa[8];
        const float4* p4 = (const float4*)(in + r * DIN);
        #pragma unroll
        for (int i = 0; i < 8; i++) xa[i] = p4[i];

        float y[DKQ];
        #pragma unroll
        for (int o = 0; o < DKQ; o++) {
            const float4* wr = (const float4*)(sW + o * DIN);
            float acc = 0.f;
            #pragma unroll
            for (int d = 0; d < 8; d++) acc = dot4(xa[d], wr[d], acc);
            y[o] = acc;
        }
        float m = 0.f;
        #pragma unroll
        for (int c = 0; c < DKQ; c++) m += y[c];
        m *= (1.f / DKQ);
        float v = 0.f;
        #pragma unroll
        for (int c = 0; c < DKQ; c++) { float d = y[c] - m; v += d * d; }
        v *= (1.f / DKQ);
        float rs = rsqrtf(v + EPS);

        if (task == 1) {
            #pragma unroll
            for (int c = 0; c < DKQ; c++) y[c] = (y[c] - m) * rs * sg[c] + sb[c];
            int mv = s_is_byte ? (int)((const unsigned char*)mask_raw)[r]
                               : ((const int*)mask_raw)[r];
            float bias = mv ? BIAS_MASKED : 0.f;   // True masks OUT
            u32 wv[KWS];
            #pragma unroll
            for (int p = 0; p < 10; p++) wv[p] = pack_f16(y[2*p], y[2*p+1]);
            wv[10] = pack_f16(bias, 0.f);
            wv[11] = 0u;
            uint4* o4 = (uint4*)(d_kb + r * KWS);
            #pragma unroll
            for (int i = 0; i < 3; i++)
                o4[i] = make_uint4(wv[4*i], wv[4*i+1], wv[4*i+2], wv[4*i+3]);
        } else {
            #pragma unroll
            for (int c = 0; c < DKQ; c++)
                y[c] = ((y[c] - m) * rs * sg[c] + sb[c]) * QSCALE;
            u32 wv[QW];
            #pragma unroll
            for (int p = 0; p < 10; p++) wv[p] = pack_f16(y[2*p], y[2*p+1]);
            wv[10] = pack_f16(1.0f, 0.f);
            #pragma unroll
            for (int p = 11; p < QW; p++) wv[p] = 0u;
            uint4* o4 = (uint4*)(d_qb + r * QW);
            #pragma unroll
            for (int i = 0; i < 4; i++)
                o4[i] = make_uint4(wv[4*i], wv[4*i+1], wv[4*i+2], wv[4*i+3]);
        }
    }
}

// ---------------------------------------------------------------------------
// Kernel 2: flash attention, f16 m16n8k16 mma + ldmatrix, cp.async
// double-buffered TS=64 tiles. ONE m16 tile per warp; grid=(LQ/64,NB)=1024.
// Compact K (12 words, zero upper-quarter fragment is a constant 0 register),
// compact V copies (16 words; ones-column pre-initialized in smem once).
// ---------------------------------------------------------------------------
#define TS 64
#define NT (LK / TS)
#define KT4 (TS * KWS / 4)   // 192 uint4 per K tile
#define VT4 (TS * VWG / 4)   // 256 uint4 per V tile

__global__ __launch_bounds__(128) void attn_kernel(
    const float* __restrict__ ques,
    const float* __restrict__ go, const float* __restrict__ bo,
    float* __restrict__ out)
{
    __shared__ u32 sK[2][TS * KWS];   // 2 x 3072 B
    __shared__ u32 sV[2][TS * VW];    // 2 x 5120 B

    int tid  = threadIdx.x;
    int w    = tid >> 5;
    int lane = tid & 31;
    int g    = lane >> 2;   // group id (0..7)
    int i    = lane & 3;    // thread in group (0..3)
    int b    = blockIdx.y;
    int qbase = blockIdx.x * 64 + w * 16;

    // ---- Q fragments: one m16 tile x two k16 chunks, in registers ----
    u32 aq[2][4];
    {
        const u32* q0p = d_qb + ((size_t)b * LQ + qbase + g) * QW;
        const u32* q1p = q0p + 8 * QW;
        #pragma unroll
        for (int c = 0; c < 2; c++) {
            aq[c][0] = q0p[8 * c + i];
            aq[c][1] = q1p[8 * c + i];
            aq[c][2] = q0p[8 * c + i + 4];
            aq[c][3] = q1p[8 * c + i + 4];
        }
    }

    // o[nt] nt=0..3: output dims; nt=4: ones-column (denominator)
    float o[5][4];
    #pragma unroll
    for (int nt = 0; nt < 5; nt++)
        #pragma unroll
        for (int r = 0; r < 4; r++) o[nt][r] = 0.f;

    const u32* kgl = d_kb + (size_t)b * LK * KWS;
    const u32* vgl = d_vb + (size_t)b * LK * VWG;

    u32 sK_u[2], sV_u[2];
    sK_u[0] = (u32)__cvta_generic_to_shared(&sK[0][0]);
    sK_u[1] = (u32)__cvta_generic_to_shared(&sK[1][0]);
    sV_u[0] = (u32)__cvta_generic_to_shared(&sV[0][0]);
    sV_u[1] = (u32)__cvta_generic_to_shared(&sV[1][0]);

    // ---- one-time: ones-column + pad words (w16..w19) for BOTH V buffers ----
    {
        int buf = tid >> 6, row = tid & 63;   // 128 threads = 2 x 64 rows
        uint4* p = (uint4*)(&sV[buf][row * VW + 16]);
        *p = make_uint4(pack_f16(1.0f, 0.f), 0u, 0u, 0u);
    }

    // ---- preamble: async load tile 0 ----
    {
        #pragma unroll
        for (int rr = 0; rr < 2; rr++) {
            int idx = tid + rr * 128;
            if (idx < KT4) cp16(sK_u[0] + idx * 16, kgl + idx * 4);
        }
        #pragma unroll
        for (int rr = 0; rr < 2; rr++) {
            int idx = tid + rr * 128;
            int row = idx >> 2, mm = idx & 3;
            cp16(sV_u[0] + (row * VW + mm * 4) * 4, vgl + idx * 4);
        }
        CP_COMMIT();
    }

    for (int t0 = 0; t0 < NT; t0++) {
        int cur = t0 & 1;
        CP_WAIT0();
        __syncthreads();   // tile t0 ready; all warps done with buffer we refill

        // prefetch tile t0+1 (overlaps with compute below)
        if (t0 + 1 < NT) {
            int nxt = cur ^ 1;
            const u32* kg2 = kgl + (size_t)(t0 + 1) * TS * KWS;
            const u32* vg2 = vgl + (size_t)(t0 + 1) * TS * VWG;
            #pragma unroll
            for (int rr = 0; rr < 2; rr++) {
                int idx = tid + rr * 128;
                if (idx < KT4) cp16(sK_u[nxt] + idx * 16, kg2 + idx * 4);
            }
            #pragma unroll
            for (int rr = 0; rr < 2; rr++) {
                int idx = tid + rr * 128;
                int row = idx >> 2, mm = idx & 3;
                cp16(sV_u[nxt] + (row * VW + mm * 4) * 4, vg2 + idx * 4);
            }
            CP_COMMIT();
        }

        #pragma unroll
        for (int kg = 0; kg < TS / 16; kg++) {
            // ---- K fragments: 8-key groups A (keys kg*16+0..7) and B (+8..15)
            // upper quarter of chunk1 (feats 24..31) is identically zero -> 0 reg
            const u32* kA = &sK[cur][(kg * 16 + g) * KWS];
            const u32* kB = kA + 8 * KWS;
            u32 kbA[3], kbB[3];
            kbA[0] = kA[i];  kbA[1] = kA[i + 4];  kbA[2] = kA[8 + i];
            kbB[0] = kB[i];  kbB[1] = kB[i + 4];  kbB[2] = kB[8 + i];

            // ---- V fragments: ldmatrix x4 (dims 0..31) + x2 (ones col 32..39)
            u32 vb0[4], vb1[4], vb40, vb41;
            {
                int rrow = lane & 7, mm = lane >> 3;
                u32 a1 = sV_u[cur] + ((kg * 16 + rrow) * VW + mm * 4) * 4;
                u32 a2 = a1 + 8 * VW * 4;
                asm volatile("ldmatrix.sync.aligned.m8n8.x4.trans.shared.b16 "
                             "{%0,%1,%2,%3}, [%4];"
                    : "=r"(vb0[0]), "=r"(vb0[1]), "=r"(vb0[2]), "=r"(vb0[3]) : "r"(a1));
                asm volatile("ldmatrix.sync.aligned.m8n8.x4.trans.shared.b16 "
                             "{%0,%1,%2,%3}, [%4];"
                    : "=r"(vb1[0]), "=r"(vb1[1]), "=r"(vb1[2]), "=r"(vb1[3]) : "r"(a2));
                u32 a3 = sV_u[cur] +
                    ((kg * 16 + (lane & 7) + ((lane >> 3) & 1) * 8) * VW + 16) * 4;
                asm volatile("ldmatrix.sync.aligned.m8n8.x2.trans.shared.b16 "
                             "{%0,%1}, [%2];"
                    : "=r"(vb40), "=r"(vb41) : "r"(a3));
            }

            // QK^T for both 8-key groups (bias included via K[20])
            float sA0 = 0.f, sA1 = 0.f, sA2 = 0.f, sA3 = 0.f;
            float sB0 = 0.f, sB1 = 0.f, sB2 = 0.f, sB3 = 0.f;
            mma_f16(sA0, sA1, sA2, sA3,
                    aq[0][0], aq[0][1], aq[0][2], aq[0][3],
                    kbA[0], kbA[1], sA0, sA1, sA2, sA3);
            mma_f16(sA0, sA1, sA2, sA3,
                    aq[1][0], aq[1][1], aq[1][2], aq[1][3],
                    kbA[2], 0u, sA0, sA1, sA2, sA3);
            mma_f16(sB0, sB1, sB2, sB3,
                    aq[0][0], aq[0][1], aq[0][2], aq[0][3],
                    kbB[0], kbB[1], sB0, sB1, sB2, sB3);
            mma_f16(sB0, sB1, sB2, sB3,
                    aq[1][0], aq[1][1], aq[1][2], aq[1][3],
                    kbB[2], 0u, sB0, sB1, sB2, sB3);

            // pack score pairs -> f16x2, dual-exp via one MUFU op each.
            // Resulting f16x2 IS the P A-fragment (no further packing).
            u32 pa0 = ex2h2(pack_f16(sA0, sA1));   // row g,   keys 2i,2i+1
            u32 pa1 = ex2h2(pack_f16(sA2, sA3));   // row g+8
            u32 pa2 = ex2h2(pack_f16(sB0, sB1));   // row g,   keys 8+2i..
            u32 pa3 = ex2h2(pack_f16(sB2, sB3));   // row g+8

            #pragma unroll
            for (int nt = 0; nt < 4; nt++) {
                mma_f16(o[nt][0], o[nt][1], o[nt][2], o[nt][3],
                        pa0, pa1, pa2, pa3, vb0[nt], vb1[nt],
                        o[nt][0], o[nt][1], o[nt][2], o[nt][3]);
            }
            // ones-column: accumulates softmax denominator per row
            mma_f16(o[4][0], o[4][1], o[4][2], o[4][3],
                    pa0, pa1, pa2, pa3, vb40, vb41,
                    o[4][0], o[4][1], o[4][2], o[4][3]);
        }
    }

    // ---- epilogue: broadcast l (ones-col, i==0 lanes), normalize, residual,
    //      LayerNorm, store ----
    {
        // l lives at col 32 -> local col 0 -> lanes with i==0
        float l0 = __shfl_sync(0xFFFFFFFFu, o[4][0], lane & 28);  // row g
        float l1 = __shfl_sync(0xFFFFFFFFu, o[4][2], lane & 28);  // row g+8
        float inv0 = 1.f / l0;
        float inv1 = 1.f / l1;

        #pragma unroll
        for (int half = 0; half < 2; half++) {
            int   row  = qbase + g + half * 8;
            float invl = half == 0 ? inv0 : inv1;
            int   r0   = half == 0 ? 0 : 2;

            const float2* qr = (const float2*)(ques + ((size_t)b * LQ + row) * DIN);
            float x[4][2];
            float ssum = 0.f;
            #pragma unroll
            for (int nt = 0; nt < 4; nt++) {
                float2 qv = qr[nt * 4 + i];
                x[nt][0] = o[nt][r0]     * invl + qv.x;
                x[nt][1] = o[nt][r0 + 1] * invl + qv.y;
                ssum += x[nt][0] + x[nt][1];
            }
            ssum += __shfl_xor_sync(0xFFFFFFFFu, ssum, 1);
            ssum += __shfl_xor_sync(0xFFFFFFFFu, ssum, 2);
            float m = ssum * (1.f / DIN);
            float v = 0.f;
            #pragma unroll
            for (int nt = 0; nt < 4; nt++) {
                float d0 = x[nt][0] - m, d1 = x[nt][1] - m;
                v += d0 * d0 + d1 * d1;
            }
            v += __shfl_xor_sync(0xFFFFFFFFu, v, 1);
            v += __shfl_xor_sync(0xFFFFFFFFu, v, 2);
            float rs = rsqrtf(v * (1.f / DIN) + EPS);

            float2* po = (float2*)(out + ((size_t)b * LQ + row) * DIN);
            #pragma unroll
            for (int nt = 0; nt < 4; nt++) {
                int col = nt * 8 + 2 * i;
                float2 tt;
                tt.x = (x[nt][0] - m) * rs * __ldg(go + col)     + __ldg(bo + col);
                tt.y = (x[nt][1] - m) * rs * __ldg(go + col + 1) + __ldg(bo + col + 1);
                po[nt * 4 + i] = tt;
            }
        }
    }
}

// ---------------------------------------------------------------------------
extern "C" void kernel_launch(void* const* d_in, const int* in_sizes, int n_in,
                              void* d_out, int out_size)
{
    const float* vals = (const float*)d_in[0];
    const float* keys = (const float*)d_in[1];
    const float* ques = (const float*)d_in[2];
    const void*  mask = d_in[3];
    const float* Wv   = (const float*)d_in[4];
    const float* Wk   = (const float*)d_in[5];
    const float* Wq   = (const float*)d_in[6];
    const float* gk   = (const float*)d_in[7];
    const float* bk   = (const float*)d_in[8];
    const float* gq   = (const float*)d_in[9];
    const float* bq   = (const float*)d_in[10];
    const float* go   = (const float*)d_in[11];
    const float* bo   = (const float*)d_in[12];
    float* out = (float*)d_out;

    dim3 pgrid((NB * LK) / 256, 3);
    proj_kernel<<<pgrid, 256>>>(vals, keys, ques, mask, Wv, Wk, Wq, gk, bk, gq, bq);

    dim3 grid(LQ / 64, NB);
    attn_kernel<<<grid, 128>>>(ques, go, bo, out);
}

// round 15
// speedup vs baseline: 1.1188x; 1.0300x over previous
#include <cuda_runtime.h>
#include <cstdint>

// Problem constants
#define NB   32
#define LQ   2048
#define LK   2048
#define DIN  32
#define DKQ  20
#define EPS  1e-5f
// fold 1/sqrt(20) * log2(e) into q so scores are in log2 domain
#define QSCALE 0.32258572299984063f   // log2(e)/sqrt(20)
#define BIAS_MASKED (-60000.0f)       // f16-finite; ex2 -> exactly 0

// f16 storage strides (in u32 words = f16 pairs)
#define KWS 12  // K row (global AND smem): feats 0..19 (w0-9), bias@w10, zero w11 -> 48B
#define VWG 16  // V row global: dims 0..31 compact -> 64B
#define VW  20  // V row smem: 16 data words + ones@w16 + zero w17-19 -> 80B
#define QW  16  // Q row: feats 0..19, 1.0@20, zero-pad to 32 f16 -> 64B

typedef unsigned int u32;

// Scratch (allocation-free rule: __device__ globals), f16 pairs as u32
__device__ u32 d_kb[(size_t)NB * LK * KWS];
__device__ u32 d_vb[(size_t)NB * LK * VWG];
__device__ u32 d_qb[(size_t)NB * LQ * QW];

// pack two f32 -> f16x2 (lo = first arg)
__device__ __forceinline__ u32 pack_f16(float lo, float hi) {
    u32 d; asm("cvt.rn.f16x2.f32 %0, %1, %2;" : "=r"(d) : "f"(hi), "f"(lo));
    return d;
}
// dual exp2 on packed f16x2
__device__ __forceinline__ u32 ex2h2(u32 a) {
    u32 d; asm("ex2.approx.f16x2 %0, %1;" : "=r"(d) : "r"(a));
    return d;
}
// m16n8k16 f16 mma: D = A*B + C (fp32 accum)
__device__ __forceinline__ void mma_f16(
    float& d0, float& d1, float& d2, float& d3,
    u32 a0, u32 a1, u32 a2, u32 a3, u32 b0, u32 b1,
    float c0, float c1, float c2, float c3)
{
    asm("mma.sync.aligned.m16n8k16.row.col.f32.f16.f16.f32 "
        "{%0,%1,%2,%3},{%4,%5,%6,%7},{%8,%9},{%10,%11,%12,%13};"
        : "=f"(d0), "=f"(d1), "=f"(d2), "=f"(d3)
        : "r"(a0), "r"(a1), "r"(a2), "r"(a3), "r"(b0), "r"(b1),
          "f"(c0), "f"(c1), "f"(c2), "f"(c3));
}
// m16n8k8 f16 mma (half-depth): covers feats 16..19 + bias + zero pad
__device__ __forceinline__ void mma_f16_k8(
    float& d0, float& d1, float& d2, float& d3,
    u32 a0, u32 a1, u32 b0,
    float c0, float c1, float c2, float c3)
{
    asm("mma.sync.aligned.m16n8k8.row.col.f32.f16.f16.f32 "
        "{%0,%1,%2,%3},{%4,%5},{%6},{%7,%8,%9,%10};"
        : "=f"(d0), "=f"(d1), "=f"(d2), "=f"(d3)
        : "r"(a0), "r"(a1), "r"(b0),
          "f"(c0), "f"(c1), "f"(c2), "f"(c3));
}
__device__ __forceinline__ void cp16(u32 dst, const void* src) {
    asm volatile("cp.async.cg.shared.global [%0], [%1], 16;" :: "r"(dst), "l"(src));
}
#define CP_COMMIT() asm volatile("cp.async.commit_group;")
#define CP_WAIT0()  asm volatile("cp.async.wait_group 0;")

__device__ __forceinline__ float dot4(float4 a, float4 b, float acc) {
    acc = fmaf(a.x, b.x, acc);
    acc = fmaf(a.y, b.y, acc);
    acc = fmaf(a.z, b.z, acc);
    acc = fmaf(a.w, b.w, acc);
    return acc;
}

// ---------------------------------------------------------------------------
// Kernel 1: projections -> f16 (compact layouts), split by blockIdx.y.
// ---------------------------------------------------------------------------
__global__ __launch_bounds__(256) void proj_kernel(
    const float* __restrict__ vals, const float* __restrict__ keys,
    const float* __restrict__ ques, const void* __restrict__ mask_raw,
    const float* __restrict__ Wv, const float* __restrict__ Wk, const float* __restrict__ Wq,
    const float* __restrict__ gk, const float* __restrict__ bk,
    const float* __restrict__ gq, const float* __restrict__ bq)
{
    __shared__ float sW[DIN * DIN];
    __shared__ float sg[DKQ], sb[DKQ];
    __shared__ int s_is_byte;

    int tid  = threadIdx.x;
    int task = blockIdx.y;
    size_t r = (size_t)blockIdx.x * 256 + tid;

    if (task == 0) {
        for (int i = tid; i < DIN * DIN; i += 256) sW[i] = Wv[i];
        __syncthreads();

        float4 xa[8];
        const float4* p4 = (const float4*)(vals + r * DIN);
        #pragma unroll
        for (int i = 0; i < 8; i++) xa[i] = p4[i];

        uint4* o4 = (uint4*)(d_vb + r * VWG);
        #pragma unroll
        for (int half = 0; half < 2; half++) {
            float outr[16];
            #pragma unroll
            for (int o = 0; o < 16; o++) {
                const float4* wr = (const float4*)(sW + (half * 16 + o) * DIN);
                float acc = 0.f;
                #pragma unroll
                for (int d = 0; d < 8; d++) acc = dot4(xa[d], wr[d], acc);
                outr[o] = acc;
            }
            u32 wv[8];
            #pragma unroll
            for (int p = 0; p < 8; p++) wv[p] = pack_f16(outr[2*p], outr[2*p+1]);
            o4[half * 2]     = make_uint4(wv[0], wv[1], wv[2], wv[3]);
            o4[half * 2 + 1] = make_uint4(wv[4], wv[5], wv[6], wv[7]);
        }
    } else {
        const float* W  = (task == 1) ? Wk : Wq;
        const float* gg = (task == 1) ? gk : gq;
        const float* bb = (task == 1) ? bk : bq;
        const float* in = (task == 1) ? keys : ques;
        for (int i = tid; i < DKQ * DIN; i += 256) sW[i] = W[i];
        if (tid < DKQ) { sg[tid] = gg[tid]; sb[tid] = bb[tid]; }
        if (task == 1 && tid == 0) {
            // Detect mask storage: numpy bool (1 byte) vs int32 coercion.
            const unsigned int* wd = (const unsigned int*)mask_raw;
            unsigned int acc = 0;
            for (int k = 0; k < 64; k++) acc |= wd[k] & 0xFFFFFF00u;
            s_is_byte = (acc != 0u);
        }
        __syncthreads();

        float4 xa[8];
        const float4* p4 = (const float4*)(in + r * DIN);
        #pragma unroll
        for (int i = 0; i < 8; i++) xa[i] = p4[i];

        float y[DKQ];
        #pragma unroll
        for (int o = 0; o < DKQ; o++) {
            const float4* wr = (const float4*)(sW + o * DIN);
            float acc = 0.f;
            #pragma unroll
            for (int d = 0; d < 8; d++) acc = dot4(xa[d], wr[d], acc);
            y[o] = acc;
        }
        float m = 0.f;
        #pragma unroll
        for (int c = 0; c < DKQ; c++) m += y[c];
        m *= (1.f / DKQ);
        float v = 0.f;
        #pragma unroll
        for (int c = 0; c < DKQ; c++) { float d = y[c] - m; v += d * d; }
        v *= (1.f / DKQ);
        float rs = rsqrtf(v + EPS);

        if (task == 1) {
            #pragma unroll
            for (int c = 0; c < DKQ; c++) y[c] = (y[c] - m) * rs * sg[c] + sb[c];
            int mv = s_is_byte ? (int)((const unsigned char*)mask_raw)[r]
                               : ((const int*)mask_raw)[r];
            float bias = mv ? BIAS_MASKED : 0.f;   // True masks OUT
            u32 wv[KWS];
            #pragma unroll
            for (int p = 0; p < 10; p++) wv[p] = pack_f16(y[2*p], y[2*p+1]);
            wv[10] = pack_f16(bias, 0.f);
            wv[11] = 0u;
            uint4* o4 = (uint4*)(d_kb + r * KWS);
            #pragma unroll
            for (int i = 0; i < 3; i++)
                o4[i] = make_uint4(wv[4*i], wv[4*i+1], wv[4*i+2], wv[4*i+3]);
        } else {
            #pragma unroll
            for (int c = 0; c < DKQ; c++)
                y[c] = ((y[c] - m) * rs * sg[c] + sb[c]) * QSCALE;
            u32 wv[QW];
            #pragma unroll
            for (int p = 0; p < 10; p++) wv[p] = pack_f16(y[2*p], y[2*p+1]);
            wv[10] = pack_f16(1.0f, 0.f);
            #pragma unroll
            for (int p = 11; p < QW; p++) wv[p] = 0u;
            uint4* o4 = (uint4*)(d_qb + r * QW);
            #pragma unroll
            for (int i = 0; i < 4; i++)
                o4[i] = make_uint4(wv[4*i], wv[4*i+1], wv[4*i+2], wv[4*i+3]);
        }
    }
}

// ---------------------------------------------------------------------------
// Kernel 2: flash attention. QK = m16n8k16 + m16n8k8 (no zero-padded depth),
// K fragments via 2 ldmatrix (was 6 LDS.32), V via ldmatrix, cp.async
// double-buffered TS=64 tiles. ONE m16 tile per warp; grid=(LQ/64,NB)=1024.
// ---------------------------------------------------------------------------
#define TS 64
#define NT (LK / TS)
#define KT4 (TS * KWS / 4)   // 192 uint4 per K tile
#define VT4 (TS * VWG / 4)   // 256 uint4 per V tile

__global__ __launch_bounds__(128) void attn_kernel(
    const float* __restrict__ ques,
    const float* __restrict__ go, const float* __restrict__ bo,
    float* __restrict__ out)
{
    __shared__ u32 sK[2][TS * KWS];   // 2 x 3072 B
    __shared__ u32 sV[2][TS * VW];    // 2 x 5120 B

    int tid  = threadIdx.x;
    int w    = tid >> 5;
    int lane = tid & 31;
    int g    = lane >> 2;   // group id (0..7)
    int i    = lane & 3;    // thread in group (0..3)
    int b    = blockIdx.y;
    int qbase = blockIdx.x * 64 + w * 16;

    // ---- Q fragments: k16 chunk (4 regs) + k8 chunk (2 regs) ----
    u32 aq0[4], aq1[2];
    {
        const u32* q0p = d_qb + ((size_t)b * LQ + qbase + g) * QW;
        const u32* q1p = q0p + 8 * QW;
        aq0[0] = q0p[i];
        aq0[1] = q1p[i];
        aq0[2] = q0p[i + 4];
        aq0[3] = q1p[i + 4];
        aq1[0] = q0p[8 + i];
        aq1[1] = q1p[8 + i];
    }

    // o[nt] nt=0..3: output dims; nt=4: ones-column (denominator)
    float o[5][4];
    #pragma unroll
    for (int nt = 0; nt < 5; nt++)
        #pragma unroll
        for (int r = 0; r < 4; r++) o[nt][r] = 0.f;

    const u32* kgl = d_kb + (size_t)b * LK * KWS;
    const u32* vgl = d_vb + (size_t)b * LK * VWG;

    u32 sK_u[2], sV_u[2];
    sK_u[0] = (u32)__cvta_generic_to_shared(&sK[0][0]);
    sK_u[1] = (u32)__cvta_generic_to_shared(&sK[1][0]);
    sV_u[0] = (u32)__cvta_generic_to_shared(&sV[0][0]);
    sV_u[1] = (u32)__cvta_generic_to_shared(&sV[1][0]);

    // ---- one-time: ones-column + pad words (w16..w19) for BOTH V buffers ----
    {
        int buf = tid >> 6, row = tid & 63;   // 128 threads = 2 x 64 rows
        uint4* p = (uint4*)(&sV[buf][row * VW + 16]);
        *p = make_uint4(pack_f16(1.0f, 0.f), 0u, 0u, 0u);
    }

    // ---- preamble: async load tile 0 ----
    {
        #pragma unroll
        for (int rr = 0; rr < 2; rr++) {
            int idx = tid + rr * 128;
            if (idx < KT4) cp16(sK_u[0] + idx * 16, kgl + idx * 4);
        }
        #pragma unroll
        for (int rr = 0; rr < 2; rr++) {
            int idx = tid + rr * 128;
            int row = idx >> 2, mm = idx & 3;
            cp16(sV_u[0] + (row * VW + mm * 4) * 4, vgl + idx * 4);
        }
        CP_COMMIT();
    }

    // per-lane constant parts of the ldmatrix-K addresses
    int kmM  = lane >> 3;          // matrix id 0..3 (x4)
    int kmR  = lane & 7;           // row within matrix
    int kOff4 = ((kmM >> 1) * 8 + kmR) * KWS + (kmM & 1) * 4;  // words
    int kOff2 = (((lane >> 3) & 1) * 8 + kmR) * KWS + 8;       // words

    for (int t0 = 0; t0 < NT; t0++) {
        int cur = t0 & 1;
        CP_WAIT0();
        __syncthreads();   // tile t0 ready; all warps done with buffer we refill

        // prefetch tile t0+1 (overlaps with compute below)
        if (t0 + 1 < NT) {
            int nxt = cur ^ 1;
            const u32* kg2 = kgl + (size_t)(t0 + 1) * TS * KWS;
            const u32* vg2 = vgl + (size_t)(t0 + 1) * TS * VWG;
            #pragma unroll
            for (int rr = 0; rr < 2; rr++) {
                int idx = tid + rr * 128;
                if (idx < KT4) cp16(sK_u[nxt] + idx * 16, kg2 + idx * 4);
            }
            #pragma unroll
            for (int rr = 0; rr < 2; rr++) {
                int idx = tid + rr * 128;
                int row = idx >> 2, mm = idx & 3;
                cp16(sV_u[nxt] + (row * VW + mm * 4) * 4, vg2 + idx * 4);
            }
            CP_COMMIT();
        }

        #pragma unroll
        for (int kg = 0; kg < TS / 16; kg++) {
            // ---- K fragments via 2 ldmatrix (non-trans) ----
            // x4: m0=rows A w0-3 -> kbA0, m1=rows A w4-7 -> kbA1,
            //     m2=rows B w0-3 -> kbB0, m3=rows B w4-7 -> kbB1
            // x2: m0=rows A w8-11 -> kbA2, m1=rows B w8-11 -> kbB2
            u32 kbA0, kbA1, kbB0, kbB1, kbA2, kbB2;
            {
                u32 a4 = sK_u[cur] + (kg * 16 * KWS + kOff4) * 4;
                asm volatile("ldmatrix.sync.aligned.m8n8.x4.shared.b16 "
                             "{%0,%1,%2,%3}, [%4];"
                    : "=r"(kbA0), "=r"(kbA1), "=r"(kbB0), "=r"(kbB1) : "r"(a4));
                u32 a2 = sK_u[cur] + (kg * 16 * KWS + kOff2) * 4;
                asm volatile("ldmatrix.sync.aligned.m8n8.x2.shared.b16 "
                             "{%0,%1}, [%2];"
                    : "=r"(kbA2), "=r"(kbB2) : "r"(a2));
            }

            // ---- V fragments: ldmatrix x4 (dims 0..31) + x2 (ones col 32..39)
            u32 vb0[4], vb1[4], vb40, vb41;
            {
                int rrow = lane & 7, mm = lane >> 3;
                u32 a1 = sV_u[cur] + ((kg * 16 + rrow) * VW + mm * 4) * 4;
                u32 a2v = a1 + 8 * VW * 4;
                asm volatile("ldmatrix.sync.aligned.m8n8.x4.trans.shared.b16 "
                             "{%0,%1,%2,%3}, [%4];"
                    : "=r"(vb0[0]), "=r"(vb0[1]), "=r"(vb0[2]), "=r"(vb0[3]) : "r"(a1));
                asm volatile("ldmatrix.sync.aligned.m8n8.x4.trans.shared.b16 "
                             "{%0,%1,%2,%3}, [%4];"
                    : "=r"(vb1[0]), "=r"(vb1[1]), "=r"(vb1[2]), "=r"(vb1[3]) : "r"(a2v));
                u32 a3 = sV_u[cur] +
                    ((kg * 16 + (lane & 7) + ((lane >> 3) & 1) * 8) * VW + 16) * 4;
                asm volatile("ldmatrix.sync.aligned.m8n8.x2.trans.shared.b16 "
                             "{%0,%1}, [%2];"
                    : "=r"(vb40), "=r"(vb41) : "r"(a3));
            }

            // QK^T: k16 MMA (feats 0..15) + k8 MMA (feats 16..19 + bias + pad)
            float sA0 = 0.f, sA1 = 0.f, sA2 = 0.f, sA3 = 0.f;
            float sB0 = 0.f, sB1 = 0.f, sB2 = 0.f, sB3 = 0.f;
            mma_f16(sA0, sA1, sA2, sA3,
                    aq0[0], aq0[1], aq0[2], aq0[3],
                    kbA0, kbA1, sA0, sA1, sA2, sA3);
            mma_f16_k8(sA0, sA1, sA2, sA3,
                       aq1[0], aq1[1], kbA2, sA0, sA1, sA2, sA3);
            mma_f16(sB0, sB1, sB2, sB3,
                    aq0[0], aq0[1], aq0[2], aq0[3],
                    kbB0, kbB1, sB0, sB1, sB2, sB3);
            mma_f16_k8(sB0, sB1, sB2, sB3,
                       aq1[0], aq1[1], kbB2, sB0, sB1, sB2, sB3);

            // pack score pairs -> f16x2, dual-exp via one MUFU op each.
            // Resulting f16x2 IS the P A-fragment (no further packing).
            u32 pa0 = ex2h2(pack_f16(sA0, sA1));   // row g,   keys 2i,2i+1
            u32 pa1 = ex2h2(pack_f16(sA2, sA3));   // row g+8
            u32 pa2 = ex2h2(pack_f16(sB0, sB1));   // row g,   keys 8+2i..
            u32 pa3 = ex2h2(pack_f16(sB2, sB3));   // row g+8

            #pragma unroll
            for (int nt = 0; nt < 4; nt++) {
                mma_f16(o[nt][0], o[nt][1], o[nt][2], o[nt][3],
                        pa0, pa1, pa2, pa3, vb0[nt], vb1[nt],
                        o[nt][0], o[nt][1], o[nt][2], o[nt][3]);
            }
            // ones-column: accumulates softmax denominator per row
            mma_f16(o[4][0], o[4][1], o[4][2], o[4][3],
                    pa0, pa1, pa2, pa3, vb40, vb41,
                    o[4][0], o[4][1], o[4][2], o[4][3]);
        }
    }

    // ---- epilogue: broadcast l (ones-col, i==0 lanes), normalize, residual,
    //      LayerNorm, store ----
    {
        // l lives at col 32 -> local col 0 -> lanes with i==0
        float l0 = __shfl_sync(0xFFFFFFFFu, o[4][0], lane & 28);  // row g
        float l1 = __shfl_sync(0xFFFFFFFFu, o[4][2], lane & 28);  // row g+8
        float inv0 = 1.f / l0;
        float inv1 = 1.f / l1;

        #pragma unroll
        for (int half = 0; half < 2; half++) {
            int   row  = qbase + g + half * 8;
            float invl = half == 0 ? inv0 : inv1;
            int   r0   = half == 0 ? 0 : 2;

            const float2* qr = (const float2*)(ques + ((size_t)b * LQ + row) * DIN);
            float x[4][2];
            float ssum = 0.f;
            #pragma unroll
            for (int nt = 0; nt < 4; nt++) {
                float2 qv = qr[nt * 4 + i];
                x[nt][0] = o[nt][r0]     * invl + qv.x;
                x[nt][1] = o[nt][r0 + 1] * invl + qv.y;
                ssum += x[nt][0] + x[nt][1];
            }
            ssum += __shfl_xor_sync(0xFFFFFFFFu, ssum, 1);
            ssum += __shfl_xor_sync(0xFFFFFFFFu, ssum, 2);
            float m = ssum * (1.f / DIN);
            float v = 0.f;
            #pragma unroll
            for (int nt = 0; nt < 4; nt++) {
                float d0 = x[nt][0] - m, d1 = x[nt][1] - m;
                v += d0 * d0 + d1 * d1;
            }
            v += __shfl_xor_sync(0xFFFFFFFFu, v, 1);
            v += __shfl_xor_sync(0xFFFFFFFFu, v, 2);
            float rs = rsqrtf(v * (1.f / DIN) + EPS);

            float2* po = (float2*)(out + ((size_t)b * LQ + row) * DIN);
            #pragma unroll
            for (int nt = 0; nt < 4; nt++) {
                int col = nt * 8 + 2 * i;
                float2 tt;
                tt.x = (x[nt][0] - m) * rs * __ldg(go + col)     + __ldg(bo + col);
                tt.y = (x[nt][1] - m) * rs * __ldg(go + col + 1) + __ldg(bo + col + 1);
                po[nt * 4 + i] = tt;
            }
        }
    }
}

// ---------------------------------------------------------------------------
extern "C" void kernel_launch(void* const* d_in, const int* in_sizes, int n_in,
                              void* d_out, int out_size)
{
    const float* vals = (const float*)d_in[0];
    const float* keys = (const float*)d_in[1];
    const float* ques = (const float*)d_in[2];
    const void*  mask = d_in[3];
    const float* Wv   = (const float*)d_in[4];
    const float* Wk   = (const float*)d_in[5];
    const float* Wq   = (const float*)d_in[6];
    const float* gk   = (const float*)d_in[7];
    const float* bk   = (const float*)d_in[8];
    const float* gq   = (const float*)d_in[9];
    const float* bq   = (const float*)d_in[10];
    const float* go   = (const float*)d_in[11];
    const float* bo   = (const float*)d_in[12];
    float* out = (float*)d_out;

    dim3 pgrid((NB * LK) / 256, 3);
    proj_kernel<<<pgrid, 256>>>(vals, keys, ques, mask, Wv, Wk, Wq, gk, bk, gq, bq);

    dim3 grid(LQ / 64, NB);
    attn_kernel<<<grid, 128>>>(ques, go, bo, out);
}